// round 17
// baseline (speedup 1.0000x reference)
#include <cuda_runtime.h>
#include <cuda_fp16.h>
#include <cstdint>

typedef unsigned long long ull;

#define N_NODES 16384
#define N_EDGES 524288
#define N_LBL   131072

// ---- output layout (flattened float32 concat in reference-return order) ----
#define O_SAGE1 0ull
#define L_SAGE1 (16384ull*128ull)
#define O_Z     (O_SAGE1 + L_SAGE1)
#define L_Z     (16384ull*64ull)
#define O_DMUL  (O_Z + L_Z)
#define L_DMUL  (131072ull*64ull)
#define O_DSUM  (O_DMUL + L_DMUL)
#define L_DSUM  (131072ull)
#define O_PADJ  (O_DSUM + L_DSUM)
#define L_PADJ  (16384ull*16384ull)
#define O_MASK  (O_PADJ + L_PADJ)

// ---- scratch (device globals; no allocation allowed) ----
__device__ __align__(16) float g_agg1[N_NODES * 128];
__device__ __align__(16) float g_y1[N_NODES * 64];     // y1 = sage1 @ W_l2
__device__ __align__(16) float g_agg2[N_NODES * 64];
__device__ __align__(16) float g_deg[N_NODES];
// exact 2-way fp16 split of z: z = h + m (residual ~2^-23 |z|)
__device__ __align__(16) __half g_zh[N_NODES * 64];
__device__ __align__(16) __half g_zm[N_NODES * 64];

// ============================================================
// zero scratch: g_agg1 (524288 f4) + deg (4096 f4)   [agg2 zeroed in scatter1]
// ============================================================
__global__ void k_zero() {
    unsigned i = blockIdx.x * 256u + threadIdx.x;
    float4 zv = make_float4(0.f, 0.f, 0.f, 0.f);
    if (i < 524288u) {
        reinterpret_cast<float4*>(g_agg1)[i] = zv;
    } else if (i < 528384u) {
        reinterpret_cast<float4*>(g_deg)[i - 524288u] = zv;
    }
}

// ============================================================
// scatter1: one warp per edge, 128 ch, float4 vector atomics.
// First 1024 CTAs also zero g_agg2 (done before scatter2 launches).
// ============================================================
__global__ void k_scatter1(const float* __restrict__ x,
                           const int* __restrict__ src, const int* __restrict__ dst) {
    if (blockIdx.x < 1024u) {
        reinterpret_cast<float4*>(g_agg2)[blockIdx.x * 256u + threadIdx.x] =
            make_float4(0.f, 0.f, 0.f, 0.f);
    }
    unsigned t = blockIdx.x * 256u + threadIdx.x;
    unsigned e = t >> 5, lane = t & 31u;
    if (e >= N_EDGES) return;
    int s = src[e], d = dst[e];
    float4 v = reinterpret_cast<const float4*>(x + (size_t)s * 128)[lane];
    atomicAdd(reinterpret_cast<float4*>(g_agg1 + (size_t)d * 128 + lane * 4), v);
    if (lane == 0) atomicAdd(g_deg + d, 1.0f);
}

// ============================================================
// scatter2: half-warp per edge, 64 ch (reads pre-applied y1)
// ============================================================
__global__ void k_scatter2(const int* __restrict__ src, const int* __restrict__ dst) {
    unsigned t = blockIdx.x * 256u + threadIdx.x;
    unsigned e = t >> 4, lane = t & 15u;
    if (e >= N_EDGES) return;
    int s = src[e], d = dst[e];
    float4 v = reinterpret_cast<const float4*>(g_y1 + (size_t)s * 64)[lane];
    atomicAdd(reinterpret_cast<float4*>(g_agg2 + (size_t)d * 64 + lane * 4), v);
}

// ============================================================
// Layer 1 (FUSED): sage1 = relu( mean1 @ W_l1 + b_l1 + x @ W_r1 )
//                  y1    = sage1 @ W_l2   (epilogue, bitwise == old gemm_pre)
// Block 64 rows x 128 cols, 256 threads, thread tile 4x8 (mainloop),
// then 2x8 over 64x64 output (fused part), sage1 block staged in Ws @ stride 132.
// ============================================================
#define YS_STRIDE 68
__global__ void __launch_bounds__(256, 3) k_gemm1(const float* __restrict__ x,
                                                  const float* __restrict__ Wl,
                                                  const float* __restrict__ Wr,
                                                  const float* __restrict__ bias,
                                                  const float* __restrict__ Wl2,
                                                  float* __restrict__ out) {
    __shared__ float Ws[64 * 132];           // mainloop W chunks (stride 128) / sage1 block (stride 132)
    __shared__ float Ys[64 * YS_STRIDE];     // mainloop Y chunks / Wl2 chunks (stride 64)
    const int t = threadIdx.x;
    const int row0 = blockIdx.x * 64;
    const int tr = t >> 4, tc = t & 15;

    float acc[4][8];
#pragma unroll
    for (int jj = 0; jj < 8; jj++) {
        float bv = bias[tc * 8 + jj];
#pragma unroll
        for (int ii = 0; ii < 4; ii++) acc[ii][jj] = bv;
    }

    for (int c = 0; c < 4; c++) {
        for (int i = t; i < 2048; i += 256) {
            int l = i >> 5, q = i & 31;
            int g = c * 64 + l;
            float4 v = (g < 128)
                ? reinterpret_cast<const float4*>(Wl + (size_t)g * 128)[q]
                : reinterpret_cast<const float4*>(Wr + (size_t)(g - 128) * 128)[q];
            reinterpret_cast<float4*>(Ws + l * 128)[q] = v;
        }
        for (int i = t; i < 1024; i += 256) {
            int r = i >> 4, q = i & 15;
            int n = row0 + r;
            float4 v;
            if (c < 2) {
                v = reinterpret_cast<const float4*>(g_agg1 + (size_t)n * 128 + c * 64)[q];
                float s = 1.0f / fmaxf(g_deg[n], 1.0f);
                v.x *= s; v.y *= s; v.z *= s; v.w *= s;
            } else {
                v = reinterpret_cast<const float4*>(x + (size_t)n * 128 + (c - 2) * 64)[q];
            }
            reinterpret_cast<float4*>(Ys + r * YS_STRIDE)[q] = v;
        }
        __syncthreads();
#pragma unroll 4
        for (int k = 0; k < 64; k++) {
            float a[4];
#pragma unroll
            for (int ii = 0; ii < 4; ii++) a[ii] = Ys[(4 * tr + ii) * YS_STRIDE + k];
            float w[8];
            *reinterpret_cast<float4*>(w)     = *reinterpret_cast<const float4*>(Ws + k * 128 + tc * 8);
            *reinterpret_cast<float4*>(w + 4) = *reinterpret_cast<const float4*>(Ws + k * 128 + tc * 8 + 4);
#pragma unroll
            for (int ii = 0; ii < 4; ii++)
#pragma unroll
                for (int jj = 0; jj < 8; jj++) acc[ii][jj] = fmaf(a[ii], w[jj], acc[ii][jj]);
        }
        __syncthreads();
    }

    // ---- epilogue: relu -> global sage1 AND smem block (stride 132) ----
#pragma unroll
    for (int ii = 0; ii < 4; ii++) {
        float4 v0 = make_float4(fmaxf(acc[ii][0], 0.f), fmaxf(acc[ii][1], 0.f),
                                fmaxf(acc[ii][2], 0.f), fmaxf(acc[ii][3], 0.f));
        float4 v1 = make_float4(fmaxf(acc[ii][4], 0.f), fmaxf(acc[ii][5], 0.f),
                                fmaxf(acc[ii][6], 0.f), fmaxf(acc[ii][7], 0.f));
        size_t off = (size_t)(row0 + 4 * tr + ii) * 128 + tc * 8;
        *reinterpret_cast<float4*>(out + off)     = v0;
        *reinterpret_cast<float4*>(out + off + 4) = v1;
        *reinterpret_cast<float4*>(Ws + (4 * tr + ii) * 132 + tc * 8)     = v0;
        *reinterpret_cast<float4*>(Ws + (4 * tr + ii) * 132 + tc * 8 + 4) = v1;
    }
    __syncthreads();

    // ---- fused: y1 = sage1_blk @ Wl2 (same chunk/FMA order as old gemm_pre) ----
    const int tr2 = t >> 3, tc2 = t & 7;
    float acc2[2][8];
#pragma unroll
    for (int ii = 0; ii < 2; ii++)
#pragma unroll
        for (int jj = 0; jj < 8; jj++) acc2[ii][jj] = 0.f;

    for (int c = 0; c < 2; c++) {
        for (int i = t; i < 1024; i += 256) {
            int l = i >> 4, q = i & 15;
            reinterpret_cast<float4*>(Ys + l * 64)[q] =
                reinterpret_cast<const float4*>(Wl2 + (size_t)(c * 64 + l) * 64)[q];
        }
        __syncthreads();
#pragma unroll 8
        for (int k = 0; k < 64; k++) {
            float a0 = Ws[(2 * tr2) * 132 + c * 64 + k];
            float a1 = Ws[(2 * tr2 + 1) * 132 + c * 64 + k];
            float w[8];
            *reinterpret_cast<float4*>(w)     = *reinterpret_cast<const float4*>(Ys + k * 64 + tc2 * 8);
            *reinterpret_cast<float4*>(w + 4) = *reinterpret_cast<const float4*>(Ys + k * 64 + tc2 * 8 + 4);
#pragma unroll
            for (int jj = 0; jj < 8; jj++) {
                acc2[0][jj] = fmaf(a0, w[jj], acc2[0][jj]);
                acc2[1][jj] = fmaf(a1, w[jj], acc2[1][jj]);
            }
        }
        __syncthreads();
    }
#pragma unroll
    for (int ii = 0; ii < 2; ii++) {
        size_t off = (size_t)(row0 + 2 * tr2 + ii) * 64 + tc2 * 8;
        *reinterpret_cast<float4*>(g_y1 + off)     = make_float4(acc2[ii][0], acc2[ii][1], acc2[ii][2], acc2[ii][3]);
        *reinterpret_cast<float4*>(g_y1 + off + 4) = make_float4(acc2[ii][4], acc2[ii][5], acc2[ii][6], acc2[ii][7]);
    }
}

// ============================================================
// Layer 2: z = mean(y1-agg) + b_l2 + sage1 @ W_r2  (K=128)
// Block 64 rows x 64 cols, thread tile 2x8. Fused fp16 split epilogue.
// ============================================================
__global__ void __launch_bounds__(256) k_gemm2(const float* __restrict__ sage1,
                                               const float* __restrict__ Wr,
                                               const float* __restrict__ bias,
                                               float* __restrict__ out) {
    __shared__ float Ws[64 * 64];
    __shared__ float Ys[64 * YS_STRIDE];
    const int t = threadIdx.x;
    const int row0 = blockIdx.x * 64;
    const int tr = t >> 3, tc = t & 7;

    float acc[2][8];
#pragma unroll
    for (int ii = 0; ii < 2; ii++) {
        const int n = row0 + 2 * tr + ii;
        const float sdeg = 1.0f / fmaxf(g_deg[n], 1.0f);
        float4 a0 = reinterpret_cast<const float4*>(g_agg2 + (size_t)n * 64 + tc * 8)[0];
        float4 a1 = reinterpret_cast<const float4*>(g_agg2 + (size_t)n * 64 + tc * 8)[1];
        acc[ii][0] = bias[tc * 8 + 0] + sdeg * a0.x;
        acc[ii][1] = bias[tc * 8 + 1] + sdeg * a0.y;
        acc[ii][2] = bias[tc * 8 + 2] + sdeg * a0.z;
        acc[ii][3] = bias[tc * 8 + 3] + sdeg * a0.w;
        acc[ii][4] = bias[tc * 8 + 4] + sdeg * a1.x;
        acc[ii][5] = bias[tc * 8 + 5] + sdeg * a1.y;
        acc[ii][6] = bias[tc * 8 + 6] + sdeg * a1.z;
        acc[ii][7] = bias[tc * 8 + 7] + sdeg * a1.w;
    }

    for (int c = 0; c < 2; c++) {
        for (int i = t; i < 1024; i += 256) {
            int l = i >> 4, q = i & 15;
            reinterpret_cast<float4*>(Ws + l * 64)[q] =
                reinterpret_cast<const float4*>(Wr + (size_t)(c * 64 + l) * 64)[q];
        }
        for (int i = t; i < 1024; i += 256) {
            int r = i >> 4, q = i & 15;
            reinterpret_cast<float4*>(Ys + r * YS_STRIDE)[q] =
                reinterpret_cast<const float4*>(sage1 + (size_t)(row0 + r) * 128 + c * 64)[q];
        }
        __syncthreads();
#pragma unroll 8
        for (int k = 0; k < 64; k++) {
            float a0 = Ys[(2 * tr) * YS_STRIDE + k];
            float a1 = Ys[(2 * tr + 1) * YS_STRIDE + k];
            float w[8];
            *reinterpret_cast<float4*>(w)     = *reinterpret_cast<const float4*>(Ws + k * 64 + tc * 8);
            *reinterpret_cast<float4*>(w + 4) = *reinterpret_cast<const float4*>(Ws + k * 64 + tc * 8 + 4);
#pragma unroll
            for (int jj = 0; jj < 8; jj++) {
                acc[0][jj] = fmaf(a0, w[jj], acc[0][jj]);
                acc[1][jj] = fmaf(a1, w[jj], acc[1][jj]);
            }
        }
        __syncthreads();
    }
#pragma unroll
    for (int ii = 0; ii < 2; ii++) {
        size_t off = (size_t)(row0 + 2 * tr + ii) * 64 + tc * 8;
        *reinterpret_cast<float4*>(out + off)     = make_float4(acc[ii][0], acc[ii][1], acc[ii][2], acc[ii][3]);
        *reinterpret_cast<float4*>(out + off + 4) = make_float4(acc[ii][4], acc[ii][5], acc[ii][6], acc[ii][7]);

        // fused exact fp16 split: z = h + m
        __align__(16) __half hs[8];
        __align__(16) __half ms[8];
#pragma unroll
        for (int jj = 0; jj < 8; jj++) {
            float v = acc[ii][jj];
            __half h = __float2half_rn(v);
            float r1 = v - __half2float(h);
            __half m = __float2half_rn(r1);
            hs[jj] = h; ms[jj] = m;
        }
        *reinterpret_cast<uint4*>(g_zh + off) = *reinterpret_cast<uint4*>(hs);
        *reinterpret_cast<uint4*>(g_zm + off) = *reinterpret_cast<uint4*>(ms);
    }
}

// ============================================================
// decode: one warp per label edge
// ============================================================
__global__ void k_decode(const float* __restrict__ z, const int* __restrict__ elbl,
                         float* __restrict__ dmul, float* __restrict__ dsum) {
    unsigned t = blockIdx.x * 256u + threadIdx.x;
    unsigned e = t >> 5, lane = t & 31u;
    if (e >= N_LBL) return;
    int a = elbl[e], b = elbl[N_LBL + e];
    float2 za = reinterpret_cast<const float2*>(z + (size_t)a * 64)[lane];
    float2 zb = reinterpret_cast<const float2*>(z + (size_t)b * 64)[lane];
    float2 m = make_float2(za.x * zb.x, za.y * zb.y);
    reinterpret_cast<float2*>(dmul + (size_t)e * 64)[lane] = m;
    float s = m.x + m.y;
#pragma unroll
    for (int o = 16; o > 0; o >>= 1) s += __shfl_xor_sync(0xffffffffu, s, o);
    if (lane == 0) dsum[e] = s;
}

// ============================================================
// mma.sync helpers (plain PTX, valid on non-'a' sm_103 target)
// ============================================================
__device__ __forceinline__ uint32_t smem_u32(const void* p) {
    uint32_t a;
    asm("{ .reg .u64 t; cvta.to.shared.u64 t, %1; cvt.u32.u64 %0, t; }" : "=r"(a) : "l"(p));
    return a;
}
__device__ __forceinline__ void ldmx4(uint32_t* r, uint32_t addr) {
    asm volatile("ldmatrix.sync.aligned.m8n8.x4.shared.b16 {%0,%1,%2,%3}, [%4];"
                 : "=r"(r[0]), "=r"(r[1]), "=r"(r[2]), "=r"(r[3]) : "r"(addr));
}
__device__ __forceinline__ void mma_f16(float* d, const uint32_t* a, uint32_t b0, uint32_t b1) {
    asm volatile("mma.sync.aligned.m16n8k16.row.col.f32.f16.f16.f32 "
                 "{%0,%1,%2,%3}, {%4,%5,%6,%7}, {%8,%9}, {%0,%1,%2,%3};"
                 : "+f"(d[0]), "+f"(d[1]), "+f"(d[2]), "+f"(d[3])
                 : "r"(a[0]), "r"(a[1]), "r"(a[2]), "r"(a[3]), "r"(b0), "r"(b1));
}

// ============================================================
// big GEMM (SYMMETRIC + fp16 2-split): prob_adj = z @ z^T.
// Products: hh, mh (B=h group) and hm (B=m group) — dropped terms ~2^-23 rel.
// Lower-triangular CTA tiles only; mirror written via smem transpose (f4 I/O).
// ============================================================
#define SMEM_MM 69632
#define TSTRIDE 132

__global__ void __launch_bounds__(256, 2) k_bigmm_mma(float* __restrict__ padj,
                                                      float* __restrict__ maskp) {
    extern __shared__ char smem[];
    const uint32_t sA = smem_u32(smem);
    const uint32_t sB = sA + 32768;
    const int tid = threadIdx.x;
    const int wid = tid >> 5, lane = tid & 31;

    // triangular decode: blockIdx.x -> (bi, bj), bj <= bi
    int t = blockIdx.x;
    int bi = (int)((sqrtf(8.f * (float)t + 1.f) - 1.f) * 0.5f);
    while ((bi + 1) * (bi + 2) / 2 <= t) bi++;
    while (bi * (bi + 1) / 2 > t) bi--;
    int bj = t - bi * (bi + 1) / 2;

    // ---- fill A tiles: 2 arrays x 128 rows x 8 x 16B chunks ----
    for (int i = tid; i < 2048; i += 256) {
        int arr = i >> 10, rem = i & 1023;
        int r = rem >> 3, c = rem & 7;
        const __half* src = (arr == 0) ? g_zh : g_zm;
        uint4 v = reinterpret_cast<const uint4*>(src + (size_t)(bi * 128 + r) * 64)[c];
        *reinterpret_cast<uint4*>(smem + arr * 16384 + r * 128 + ((c ^ (r & 7)) << 4)) = v;
    }
    // ---- fill B tiles ----
    for (int i = tid; i < 2048; i += 256) {
        int arr = i >> 10, rem = i & 1023;
        int r = rem >> 3, c = rem & 7;
        const __half* src = (arr == 0) ? g_zh : g_zm;
        uint4 v = reinterpret_cast<const uint4*>(src + (size_t)(bj * 128 + r) * 64)[c];
        *reinterpret_cast<uint4*>(smem + 32768 + arr * 16384 + r * 128 + ((c ^ (r & 7)) << 4)) = v;
    }
    __syncthreads();

    const int wm = (wid & 3) * 32;   // warp M offset
    const int wn = (wid >> 2) * 64;  // warp N offset
    const int lm = lane & 15, lh = lane >> 4;

    float acc[2][8][4];
#pragma unroll
    for (int mi = 0; mi < 2; mi++)
#pragma unroll
        for (int jj = 0; jj < 8; jj++)
#pragma unroll
            for (int q = 0; q < 4; q++) acc[mi][jj][q] = 0.f;

    // B=h group (g=0): A in {h, m}; B=m group (g=1): A in {h}
    const int NApg[2] = {2, 1};

#pragma unroll
    for (int ks = 0; ks < 4; ks++) {
        const int ch = ks * 2 + lh;          // 16B k-chunk index (0..7)
        uint32_t af[2][2][4];
#pragma unroll
        for (int arr = 0; arr < 2; arr++)
#pragma unroll
            for (int mi = 0; mi < 2; mi++) {
                int r = wm + mi * 16 + lm;
                ldmx4(af[arr][mi], sA + arr * 16384 + r * 128 + ((ch ^ (r & 7)) << 4));
            }
#pragma unroll
        for (int g = 0; g < 2; g++) {
            uint32_t bfr[4][4];
#pragma unroll
            for (int nb = 0; nb < 4; nb++) {
                int r = wn + nb * 16 + lm;
                ldmx4(bfr[nb], sB + g * 16384 + r * 128 + ((ch ^ (r & 7)) << 4));
            }
#pragma unroll
            for (int a = 0; a < 2; a++) {
                if (a < NApg[g]) {
#pragma unroll
                    for (int mi = 0; mi < 2; mi++)
#pragma unroll
                        for (int nb = 0; nb < 4; nb++) {
                            mma_f16(acc[mi][nb * 2 + 0], af[a][mi], bfr[nb][0], bfr[nb][2]);
                            mma_f16(acc[mi][nb * 2 + 1], af[a][mi], bfr[nb][1], bfr[nb][3]);
                        }
                }
            }
        }
    }

    // ---- direct write of block (bi, bj) ----
    const int rl = wm + (lane >> 2);          // local row (of first mi)
    const int cl = wn + (lane & 3) * 2;       // local col
    const int rowb = bi * 128 + rl;
    const int colb = bj * 128 + cl;
#pragma unroll
    for (int mi = 0; mi < 2; mi++) {
#pragma unroll
        for (int jj = 0; jj < 8; jj++) {
            const float* d = acc[mi][jj];
            size_t o0 = (size_t)(rowb + mi * 16) * 16384ull + colb + jj * 8;
            size_t o1 = o0 + 8ull * 16384ull;
            float2 v0 = make_float2(d[0], d[1]);
            float2 v1 = make_float2(d[2], d[3]);
            __stcs(reinterpret_cast<float2*>(padj + o0), v0);
            __stcs(reinterpret_cast<float2*>(padj + o1), v1);
            float2 m0 = make_float2(v0.x > 0.f ? 1.f : 0.f, v0.y > 0.f ? 1.f : 0.f);
            float2 m1 = make_float2(v1.x > 0.f ? 1.f : 0.f, v1.y > 0.f ? 1.f : 0.f);
            __stcs(reinterpret_cast<float2*>(maskp + o0), m0);
            __stcs(reinterpret_cast<float2*>(maskp + o1), m1);
        }
    }

    // ---- mirrored write of block (bj, bi) via smem transpose ----
    if (bi != bj) {
        __syncthreads();
        float* smt = reinterpret_cast<float*>(smem);
#pragma unroll
        for (int mi = 0; mi < 2; mi++) {
#pragma unroll
            for (int jj = 0; jj < 8; jj++) {
                const float* d = acc[mi][jj];
                int r = rl + mi * 16;
                int c = cl + jj * 8;
                smt[(c + 0) * TSTRIDE + r]     = d[0];
                smt[(c + 1) * TSTRIDE + r]     = d[1];
                smt[(c + 0) * TSTRIDE + r + 8] = d[2];
                smt[(c + 1) * TSTRIDE + r + 8] = d[3];
            }
        }
        __syncthreads();
        // float4 write-out: one warp covers one 512B row segment
        for (int i = tid; i < 4096; i += 256) {
            int r = i >> 5, c4 = (i & 31) * 4;
            float4 v = *reinterpret_cast<const float4*>(smt + r * TSTRIDE + c4);
            size_t o = (size_t)(bj * 128 + r) * 16384ull + (size_t)bi * 128 + c4;
            __stcs(reinterpret_cast<float4*>(padj + o), v);
            float4 mk = make_float4(v.x > 0.f ? 1.f : 0.f, v.y > 0.f ? 1.f : 0.f,
                                    v.z > 0.f ? 1.f : 0.f, v.w > 0.f ? 1.f : 0.f);
            __stcs(reinterpret_cast<float4*>(maskp + o), mk);
        }
    }
}

// ============================================================
extern "C" void kernel_launch(void* const* d_in, const int* in_sizes, int n_in,
                              void* d_out, int out_size) {
    const float* x   = (const float*)d_in[0];
    const int*   ei  = (const int*)d_in[1];
    const int*   elb = (const int*)d_in[2];
    const float* Wl1 = (const float*)d_in[3];
    const float* bl1 = (const float*)d_in[4];
    const float* Wr1 = (const float*)d_in[5];
    const float* Wl2 = (const float*)d_in[6];
    const float* bl2 = (const float*)d_in[7];
    const float* Wr2 = (const float*)d_in[8];

    float* out   = (float*)d_out;
    float* sage1 = out + O_SAGE1;
    float* z     = out + O_Z;
    float* dmul  = out + O_DMUL;
    float* dsum  = out + O_DSUM;
    float* padj  = out + O_PADJ;
    float* maskp = out + O_MASK;

    (void)cudaFuncSetAttribute(k_bigmm_mma, cudaFuncAttributeMaxDynamicSharedMemorySize, SMEM_MM);

    k_zero<<<2064, 256>>>();
    k_scatter1<<<65536, 256>>>(x, ei, ei + N_EDGES);
    k_gemm1<<<256, 256>>>(x, Wl1, Wr1, bl1, Wl2, sage1);
    k_scatter2<<<32768, 256>>>(ei, ei + N_EDGES);
    k_gemm2<<<256, 256>>>(sage1, Wr2, bl2, z);
    k_decode<<<16384, 256>>>(z, elb, dmul, dsum);
    k_bigmm_mma<<<8256, 256, SMEM_MM>>>(padj, maskp);
}